// round 16
// baseline (speedup 1.0000x reference)
#include <cuda_runtime.h>
#include <cuda_bf16.h>
#include <cuda_fp16.h>
#include <cstdint>
#include <cstddef>

// Problem constants
#define BB 4
#define LL 2048
#define DM 512
#define DI 1024            // D_INNER
#define DS 16              // D_STATE
#define DTR 32             // DT_RANK
#define ML (BB*LL)         // 8192 rows

// ---------------- scratch (no allocations allowed) ----------------
__device__ float g_xdbl[(size_t)ML * 64];       // 0..31 dt_lr, 32+2n=B_n, 33+2n=C_n

__device__ __align__(256) __half g_xzh[(size_t)ML * 2 * DI];  // in_proj out (x|z), fp16
__device__ __align__(256) __half2 g_dtduh[(size_t)ML * DI];   // (dt, dt*u) packed fp16
__device__ __align__(256) __half g_ysh[(size_t)ML * DI];      // scan output, fp16
__device__ __align__(256) __half g_xh [(size_t)ML * DM];
__device__ __align__(256) __half g_w1h[(size_t)2 * DI * DM];
__device__ __align__(256) __half g_uh [(size_t)ML * DI];
__device__ __align__(256) __half g_wxh[(size_t)64 * DI];
__device__ __align__(256) __half g_yh [(size_t)ML * DI];
__device__ __align__(256) __half g_w2h[(size_t)DM * DI];

// ---------------- PTX helpers (base ISA only) ----------------
__device__ __forceinline__ uint32_t smem_u32(const void* p) {
    uint32_t a;
    asm("{ .reg .u64 t; cvta.to.shared.u64 t, %1; cvt.u32.u64 %0, t; }" : "=r"(a) : "l"(p));
    return a;
}
__device__ __forceinline__ void cp_async16(uint32_t saddr, const void* gaddr) {
    asm volatile("cp.async.cg.shared.global [%0], [%1], 16;" :: "r"(saddr), "l"(gaddr));
}
__device__ __forceinline__ void ldm_x4(uint32_t* r, uint32_t addr) {
    asm volatile("ldmatrix.sync.aligned.m8n8.x4.shared.b16 {%0,%1,%2,%3}, [%4];"
                 : "=r"(r[0]), "=r"(r[1]), "=r"(r[2]), "=r"(r[3]) : "r"(addr));
}
__device__ __forceinline__ void ldm_x2(uint32_t* r, uint32_t addr) {
    asm volatile("ldmatrix.sync.aligned.m8n8.x2.shared.b16 {%0,%1}, [%2];"
                 : "=r"(r[0]), "=r"(r[1]) : "r"(addr));
}
__device__ __forceinline__ void mma_f16(float* d, const uint32_t* a, const uint32_t* b) {
    asm volatile(
        "mma.sync.aligned.m16n8k16.row.col.f32.f16.f16.f32 "
        "{%0,%1,%2,%3}, {%4,%5,%6,%7}, {%8,%9}, {%0,%1,%2,%3};"
        : "+f"(d[0]), "+f"(d[1]), "+f"(d[2]), "+f"(d[3])
        : "r"(a[0]), "r"(a[1]), "r"(a[2]), "r"(a[3]), "r"(b[0]), "r"(b[1]));
}
__device__ __forceinline__ float ex2f(float x) {
    float y;
    asm("ex2.approx.f32 %0, %1;" : "=f"(y) : "f"(x));
    return y;
}
// XOR swizzle for 64B rows: conflict-free for 16B cp.async writes + ldmatrix
__device__ __forceinline__ uint32_t sw64(uint32_t o) { return o ^ ((o >> 3) & 0x30); }

// ---------------- math helpers ----------------
__device__ __forceinline__ float softplusf(float x) {
    return (x > 20.f) ? x : log1pf(__expf(x));
}
__device__ __forceinline__ float siluf(float x) {
    return x * __frcp_rn(1.f + __expf(-x));
}

// ---------------- fp32 -> fp16 convert (3 arrays in one launch) ----
__global__ void cvt3_half_kernel(const float* __restrict__ a, __half* __restrict__ ha, int na4,
                                 const float* __restrict__ b, __half* __restrict__ hb, int nb4,
                                 const float* __restrict__ c, __half* __restrict__ hc, int nc4) {
    int i = blockIdx.x * 256 + threadIdx.x;
    const float* src; __half* dst; int off;
    if (i < na4) { src = a; dst = ha; off = i; }
    else if (i < na4 + nb4) { src = b; dst = hb; off = i - na4; }
    else if (i < na4 + nb4 + nc4) { src = c; dst = hc; off = i - na4 - nb4; }
    else return;
    float4 v = ((const float4*)src)[off];
    __half2 h0 = __floats2half2_rn(v.x, v.y);
    __half2 h1 = __floats2half2_rn(v.z, v.w);
    ((__half2*)dst)[off * 2 + 0] = h0;
    ((__half2*)dst)[off * 2 + 1] = h1;
}

// ------- fp32 -> fp16 convert with B/C row interleave for x_proj_w ----------
__global__ void cvt_half_wx_kernel(const float* __restrict__ x, __half* __restrict__ h) {
    int i = blockIdx.x * 256 + threadIdx.x;       // over 64*DI/4 float4s
    if (i >= 64 * DI / 4) return;
    int row = i / (DI / 4);
    int off = i % (DI / 4);
    int dst = (row < 32) ? row : ((row < 48) ? 32 + 2 * (row - 32) : 33 + 2 * (row - 48));
    float4 v = ((const float4*)x)[i];
    __half2 h0 = __floats2half2_rn(v.x, v.y);
    __half2 h1 = __floats2half2_rn(v.z, v.w);
    ((__half2*)(h + (size_t)dst * DI))[off * 2 + 0] = h0;
    ((__half2*)(h + (size_t)dst * DI))[off * 2 + 1] = h1;
}

// ---------------- HMMA fp16 GEMM (HOUT: fp16 or fp32 output) -------
template <int BN, int HOUT>
__global__ __launch_bounds__(256) void mma_gemm_kernel(
    const __half* __restrict__ A, const __half* __restrict__ B,
    void* __restrict__ Cv, int K, int ldc) {
    constexpr int NWN = (BN == 128) ? 4 : 2;
    constexpr int NWM = 8 / NWN;
    constexpr int MT = (128 / NWM) / 16;
    constexpr int NT = (BN / NWN) / 8;
    constexpr int ATB = 128 * 64;
    constexpr int BTB = BN * 64;
    constexpr int STG = ATB + BTB;
    constexpr int NSEG = (128 + BN) * 4;

    extern __shared__ __align__(128) char smem[];
    const int tid = threadIdx.x;
    const int lane = tid & 31;
    const int wid = tid >> 5;
    const int warp_m = wid / NWN;
    const int warp_n = wid % NWN;
    const int bm = blockIdx.y * 128;
    const int bn = blockIdx.x * BN;

    uint32_t sb = smem_u32(smem);
    const __half* gpa = A + (size_t)bm * K;
    const __half* gpb = B + (size_t)bn * K;

    float acc[MT][NT][4];
#pragma unroll
    for (int i = 0; i < MT; i++)
#pragma unroll
        for (int j = 0; j < NT; j++)
#pragma unroll
            for (int v = 0; v < 4; v++) acc[i][j][v] = 0.f;

    const int nch = K >> 5;

#define GLOAD(stage_, k0_)                                                          \
    {                                                                               \
        _Pragma("unroll")                                                           \
        for (int i = 0; i < NSEG / 256; i++) {                                      \
            int seg = tid + i * 256;                                                \
            int q = seg & 3;                                                        \
            uint32_t soff; const __half* g;                                         \
            if (seg < 512) {                                                        \
                int r_ = seg >> 2;                                                  \
                soff = sw64(r_ * 64 + q * 16);                                      \
                g = gpa + (size_t)r_ * K + (k0_) + q * 8;                           \
            } else {                                                                \
                int r_ = (seg - 512) >> 2;                                          \
                soff = ATB + sw64(r_ * 64 + q * 16);                                \
                g = gpb + (size_t)r_ * K + (k0_) + q * 8;                           \
            }                                                                       \
            cp_async16(sb + (stage_) * STG + soff, g);                              \
        }                                                                           \
        asm volatile("cp.async.commit_group;");                                     \
    }

    GLOAD(0, 0);
    if (nch > 1) GLOAD(1, 32);

    const int arow = warp_m * (MT * 16) + (lane & 15);
    const int acolb = (lane >> 4) * 16;
    const int brow = warp_n * (NT * 8) + (lane & 7);
    const int bcolb = ((lane >> 3) & 1) * 16;

    for (int c = 0; c < nch; c++) {
        const int s = c % 3;
        if (c + 2 < nch) {
            GLOAD((c + 2) % 3, (c + 2) << 5);
            asm volatile("cp.async.wait_group 2;" ::: "memory");
        } else if (c + 1 < nch) {
            asm volatile("cp.async.wait_group 1;" ::: "memory");
        } else {
            asm volatile("cp.async.wait_group 0;" ::: "memory");
        }
        __syncthreads();

        uint32_t base = sb + s * STG;
#pragma unroll
        for (int ks = 0; ks < 2; ks++) {
            uint32_t a_f[MT][4], b_f[NT][2];
#pragma unroll
            for (int im = 0; im < MT; im++) {
                uint32_t off = sw64((arow + im * 16) * 64 + ks * 32 + acolb);
                ldm_x4(a_f[im], base + off);
            }
#pragma unroll
            for (int jn = 0; jn < NT; jn++) {
                uint32_t off = sw64((brow + jn * 8) * 64 + ks * 32 + bcolb);
                ldm_x2(b_f[jn], base + ATB + off);
            }
#pragma unroll
            for (int im = 0; im < MT; im++)
#pragma unroll
                for (int jn = 0; jn < NT; jn++)
                    mma_f16(acc[im][jn], a_f[im], b_f[jn]);
        }
        __syncthreads();
    }
#undef GLOAD

#pragma unroll
    for (int im = 0; im < MT; im++) {
        int r0 = bm + warp_m * (MT * 16) + im * 16 + (lane >> 2);
#pragma unroll
        for (int jn = 0; jn < NT; jn++) {
            int col = bn + warp_n * (NT * 8) + jn * 8 + (lane & 3) * 2;
            if (HOUT) {
                __half* Ch = (__half*)Cv;
                __half2 v0 = __floats2half2_rn(acc[im][jn][0], acc[im][jn][1]);
                __half2 v1 = __floats2half2_rn(acc[im][jn][2], acc[im][jn][3]);
                *(__half2*)(Ch + (size_t)r0 * ldc + col) = v0;
                *(__half2*)(Ch + (size_t)(r0 + 8) * ldc + col) = v1;
            } else {
                float* C = (float*)Cv;
                float2 v0; v0.x = acc[im][jn][0]; v0.y = acc[im][jn][1];
                float2 v1; v1.x = acc[im][jn][2]; v1.y = acc[im][jn][3];
                *(float2*)(C + (size_t)r0 * ldc + col) = v0;
                *(float2*)(C + (size_t)(r0 + 8) * ldc + col) = v1;
            }
        }
    }
}

#define GSMEM128 (3 * (128 * 64 + 128 * 64))  // 49152
#define GSMEM64  (3 * (128 * 64 + 64 * 64))   // 36864

// ----- dt SGEMM (K=32): dt = softplus(x_dbl[:,0:32] @ dt_proj_w^T + b)
// reads u as fp16; writes packed __half2 (dt, dt*u) into dtduh
__global__ void sgemm_dt_kernel(const float* __restrict__ A, const float* __restrict__ W,
                                const float* __restrict__ bias, const __half* __restrict__ uh,
                                __half2* __restrict__ dtduh) {
    __shared__ float As[16 * 132];
    __shared__ float Bs[16 * 68];
    const int tid = threadIdx.x;
    const int tx = tid & 15;
    const int ty = tid >> 4;
    const int bm = blockIdx.y * 128;
    const int bn = blockIdx.x * 64;

    const float* Ab = A + (size_t)bm * 64;
    const float* Wb = W + (size_t)bn * DTR;

    float acc[8][4];
#pragma unroll
    for (int i = 0; i < 8; i++)
#pragma unroll
        for (int j = 0; j < 4; j++) acc[i][j] = 0.f;

    for (int k0 = 0; k0 < DTR; k0 += 16) {
#pragma unroll
        for (int i = 0; i < 2; i++) {
            int qid = tid + i * 256;
            int r = qid >> 2, q = qid & 3;
            float4 v = *(const float4*)(Ab + (size_t)r * 64 + k0 + q * 4);
            As[(q * 4 + 0) * 132 + r] = v.x;
            As[(q * 4 + 1) * 132 + r] = v.y;
            As[(q * 4 + 2) * 132 + r] = v.z;
            As[(q * 4 + 3) * 132 + r] = v.w;
        }
        {
            int r = tid >> 2, q = tid & 3;
            float4 v = *(const float4*)(Wb + (size_t)r * DTR + k0 + q * 4);
            Bs[(q * 4 + 0) * 68 + r] = v.x;
            Bs[(q * 4 + 1) * 68 + r] = v.y;
            Bs[(q * 4 + 2) * 68 + r] = v.z;
            Bs[(q * 4 + 3) * 68 + r] = v.w;
        }
        __syncthreads();
#pragma unroll
        for (int k = 0; k < 16; k++) {
            float4 a0 = *(const float4*)(As + k * 132 + ty * 8);
            float4 a1 = *(const float4*)(As + k * 132 + ty * 8 + 4);
            float4 b0 = *(const float4*)(Bs + k * 68 + tx * 4);
            float a[8] = {a0.x, a0.y, a0.z, a0.w, a1.x, a1.y, a1.z, a1.w};
            float bb[4] = {b0.x, b0.y, b0.z, b0.w};
#pragma unroll
            for (int i = 0; i < 8; i++)
#pragma unroll
                for (int j = 0; j < 4; j++) acc[i][j] = fmaf(a[i], bb[j], acc[i][j]);
        }
        __syncthreads();
    }

#pragma unroll
    for (int i = 0; i < 8; i++) {
        int row = bm + ty * 8 + i;
        int col = bn + tx * 4;
        __half2 u01 = *(const __half2*)(uh + (size_t)row * DI + col);
        __half2 u23 = *(const __half2*)(uh + (size_t)row * DI + col + 2);
        float u0 = __half2float(u01.x), u1 = __half2float(u01.y);
        float u2 = __half2float(u23.x), u3 = __half2float(u23.y);
        float d0 = softplusf(acc[i][0] + bias[col + 0]);
        float d1 = softplusf(acc[i][1] + bias[col + 1]);
        float d2 = softplusf(acc[i][2] + bias[col + 2]);
        float d3 = softplusf(acc[i][3] + bias[col + 3]);
        __half2 p0 = __floats2half2_rn(d0, d0 * u0);
        __half2 p1 = __floats2half2_rn(d1, d1 * u1);
        __half2 p2 = __floats2half2_rn(d2, d2 * u2);
        __half2 p3 = __floats2half2_rn(d3, d3 * u3);
        uint4 pk;
        pk.x = *(uint32_t*)&p0; pk.y = *(uint32_t*)&p1;
        pk.z = *(uint32_t*)&p2; pk.w = *(uint32_t*)&p3;
        *(uint4*)(dtduh + (size_t)row * DI + col) = pk;
    }
}

// ------- depthwise causal conv + bias + SiLU; 4 timesteps/thread -------------
// xz now fp16; outputs fp16 u.
__global__ void conv_silu_kernel(const __half* __restrict__ xzh, const float* __restrict__ w,
                                 const float* __restrict__ b, __half* __restrict__ uh) {
    int idx = blockIdx.x * 256 + threadIdx.x;     // ML*DI/4 threads
    if (idx >= ML * DI / 4) return;
    int d = idx & (DI - 1);
    int t4 = idx >> 10;                           // 0..2047
    int bb = t4 >> 9;
    int l0 = (t4 & 511) * 4;
    size_t base = ((size_t)bb * LL + l0) * (2 * DI) + d;

    float w0 = w[d * 4 + 0], w1 = w[d * 4 + 1], w2 = w[d * 4 + 2], w3 = w[d * 4 + 3];
    float bias = b[d];

    float xm3 = 0.f, xm2 = 0.f, xm1 = 0.f;
    if (l0 > 0) {
        xm3 = __half2float(xzh[base - 3 * (size_t)(2 * DI)]);
        xm2 = __half2float(xzh[base - 2 * (size_t)(2 * DI)]);
        xm1 = __half2float(xzh[base - 1 * (size_t)(2 * DI)]);
    }
    float x0 = __half2float(xzh[base + 0 * (size_t)(2 * DI)]);
    float x1 = __half2float(xzh[base + 1 * (size_t)(2 * DI)]);
    float x2 = __half2float(xzh[base + 2 * (size_t)(2 * DI)]);
    float x3 = __half2float(xzh[base + 3 * (size_t)(2 * DI)]);

    float s0 = siluf(fmaf(w3, x0, fmaf(w2, xm1, fmaf(w1, xm2, fmaf(w0, xm3, bias)))));
    float s1 = siluf(fmaf(w3, x1, fmaf(w2, x0,  fmaf(w1, xm1, fmaf(w0, xm2, bias)))));
    float s2 = siluf(fmaf(w3, x2, fmaf(w2, x1,  fmaf(w1, x0,  fmaf(w0, xm1, bias)))));
    float s3 = siluf(fmaf(w3, x3, fmaf(w2, x2,  fmaf(w1, x1,  fmaf(w0, x0,  bias)))));

    size_t ob = ((size_t)bb * LL + l0) * DI + d;
    uh[ob + 0 * DI] = __float2half_rn(s0);
    uh[ob + 1 * DI] = __float2half_rn(s1);
    uh[ob + 2 * DI] = __float2half_rn(s2);
    uh[ob + 3 * DI] = __float2half_rn(s3);
}

// ------- selective scan: 8 lanes/channel, 2 states/lane, SW-pipelined --------
#define SU 8
__global__ __launch_bounds__(64) void scan_kernel(
    const __half2* __restrict__ dtduh, const float* __restrict__ xdbl,
    const float* __restrict__ A_log, __half* __restrict__ ysh) {
    int grp = threadIdx.x >> 3;       // 8 channel-groups per 64-thread block
    int sub = threadIdx.x & 7;        // lane within channel (states 2sub, 2sub+1)
    int ch = blockIdx.x * 8 + grp;
    int b = ch >> 10;
    int d = ch & (DI - 1);

    const float LOG2E = 1.4426950408889634f;
    float An0 = -__expf(A_log[d * DS + 2 * sub + 0]) * LOG2E;
    float An1 = -__expf(A_log[d * DS + 2 * sub + 1]) * LOG2E;

    const __half2* ddp = dtduh + (size_t)b * LL * DI + d;                           // +t*DI
    const float4* bcp = (const float4*)(xdbl + (size_t)b * LL * 64 + 32 + 4 * sub); // +t*16
    __half* yp = ysh + (size_t)b * LL * DI + d;

    float h0 = 0.f, h1 = 0.f;
    __half2 cdd[SU]; float4 cbc[SU];
#pragma unroll
    for (int j = 0; j < SU; j++) {
        cdd[j] = __ldg(ddp + (size_t)j * DI);
        cbc[j] = __ldg(bcp + (size_t)j * 16);
    }
    for (int t0 = 0; t0 < LL; t0 += SU) {
        __half2 ndd[SU]; float4 nbc[SU];
        if (t0 + SU < LL) {
#pragma unroll
            for (int j = 0; j < SU; j++) {
                size_t o = (size_t)(t0 + SU + j);
                ndd[j] = __ldg(ddp + o * DI);
                nbc[j] = __ldg(bcp + o * 16);
            }
        }
#pragma unroll
        for (int j = 0; j < SU; j++) {
            float dt  = __half2float(cdd[j].x);
            float dtu = __half2float(cdd[j].y);
            float dA0 = ex2f(dt * An0);
            float dA1 = ex2f(dt * An1);
            h0 = fmaf(dA0, h0, dtu * cbc[j].x);   // B_2s
            h1 = fmaf(dA1, h1, dtu * cbc[j].z);   // B_2s+1
            float p = fmaf(h1, cbc[j].w, h0 * cbc[j].y);
            p += __shfl_xor_sync(0xffffffffu, p, 4, 8);
            p += __shfl_xor_sync(0xffffffffu, p, 2, 8);
            p += __shfl_xor_sync(0xffffffffu, p, 1, 8);
            if (sub == 0) yp[(size_t)(t0 + j) * DI] = __float2half_rn(p);
        }
#pragma unroll
        for (int j = 0; j < SU; j++) { cdd[j] = ndd[j]; cbc[j] = nbc[j]; }
    }
}

// ------- gate: y = (ys + u*D) * silu(z) -> fp16 (all streams fp16) -----------
__global__ void gate_kernel(const __half* __restrict__ ysh, const __half* __restrict__ uh,
                            const __half* __restrict__ xzh, const float* __restrict__ Dskip,
                            __half* __restrict__ yh) {
    int idx = blockIdx.x * 256 + threadIdx.x;
    if (idx >= ML * DI) return;
    int d = idx & (DI - 1);
    size_t bl = (size_t)(idx >> 10);
    float z = __half2float(xzh[bl * (2 * DI) + DI + d]);
    float u = __half2float(uh[idx]);
    float ysv = __half2float(ysh[idx]);
    float y = fmaf(u, Dskip[d], ysv) * siluf(z);
    yh[idx] = __float2half_rn(y);
}

// ---------------- LayerNorm ---------------------------------------
__global__ void ln_kernel(float* __restrict__ io, const float* __restrict__ w,
                          const float* __restrict__ b) {
    __shared__ float ssum[4], ssq[4];
    int row = blockIdx.x;
    float* p = io + (size_t)row * DM;
    int t = threadIdx.x;
    float4 v = ((float4*)p)[t];
    float s = v.x + v.y + v.z + v.w;
    float q = v.x * v.x + v.y * v.y + v.z * v.z + v.w * v.w;
#pragma unroll
    for (int o = 16; o; o >>= 1) {
        s += __shfl_xor_sync(0xffffffffu, s, o);
        q += __shfl_xor_sync(0xffffffffu, q, o);
    }
    if ((t & 31) == 0) { ssum[t >> 5] = s; ssq[t >> 5] = q; }
    __syncthreads();
    s = ssum[0] + ssum[1] + ssum[2] + ssum[3];
    q = ssq[0] + ssq[1] + ssq[2] + ssq[3];
    float mu = s * (1.f / DM);
    float var = q * (1.f / DM) - mu * mu;
    float inv = rsqrtf(var + 1e-5f);
    int c = t * 4;
    float4 o;
    o.x = (v.x - mu) * inv * w[c + 0] + b[c + 0];
    o.y = (v.y - mu) * inv * w[c + 1] + b[c + 1];
    o.z = (v.z - mu) * inv * w[c + 2] + b[c + 2];
    o.w = (v.w - mu) * inv * w[c + 3] + b[c + 3];
    ((float4*)p)[t] = o;
}

// ---------------- launch ------------------------------------------
extern "C" void kernel_launch(void* const* d_in, const int* in_sizes, int n_in,
                              void* d_out, int out_size) {
    const float* x_in      = (const float*)d_in[0];
    const float* in_proj_w = (const float*)d_in[1];
    const float* conv_w    = (const float*)d_in[2];
    const float* conv_b    = (const float*)d_in[3];
    const float* x_proj_w  = (const float*)d_in[4];
    const float* dt_proj_w = (const float*)d_in[5];
    const float* dt_proj_b = (const float*)d_in[6];
    const float* A_log     = (const float*)d_in[7];
    const float* D_skip    = (const float*)d_in[8];
    const float* out_proj_w= (const float*)d_in[9];
    const float* ln_w      = (const float*)d_in[10];
    const float* ln_b      = (const float*)d_in[11];
    float* out = (float*)d_out;

    static float *p_xdbl=nullptr;
    static __half2 *p_dtduh;
    static __half *p_xzh,*p_ysh,*p_xh,*p_w1h,*p_uh,*p_wxh,*p_yh,*p_w2h;
    if (!p_xdbl) {
        cudaGetSymbolAddress((void**)&p_xdbl, g_xdbl);
        cudaGetSymbolAddress((void**)&p_xzh, g_xzh);
        cudaGetSymbolAddress((void**)&p_dtduh, g_dtduh);
        cudaGetSymbolAddress((void**)&p_ysh, g_ysh);
        cudaGetSymbolAddress((void**)&p_xh, g_xh);
        cudaGetSymbolAddress((void**)&p_w1h, g_w1h);
        cudaGetSymbolAddress((void**)&p_uh, g_uh);
        cudaGetSymbolAddress((void**)&p_wxh, g_wxh);
        cudaGetSymbolAddress((void**)&p_yh, g_yh);
        cudaGetSymbolAddress((void**)&p_w2h, g_w2h);
        cudaFuncSetAttribute((const void*)mma_gemm_kernel<128,0>, cudaFuncAttributeMaxDynamicSharedMemorySize, GSMEM128);
        cudaFuncSetAttribute((const void*)mma_gemm_kernel<128,1>, cudaFuncAttributeMaxDynamicSharedMemorySize, GSMEM128);
        cudaFuncSetAttribute((const void*)mma_gemm_kernel<64,0>,  cudaFuncAttributeMaxDynamicSharedMemorySize, GSMEM64);
    }

    // 0) fp16 converts (x_in + in_proj_w + out_proj_w fused; wx separate for permute)
    const int na4 = ML * DM / 4, nb4 = 2 * DI * DM / 4, nc4 = DM * DI / 4;
    cvt3_half_kernel<<<(na4 + nb4 + nc4 + 255) / 256, 256>>>(
        x_in, p_xh, na4, in_proj_w, p_w1h, nb4, out_proj_w, p_w2h, nc4);
    cvt_half_wx_kernel<<<(64 * DI / 4) / 256, 256>>>(x_proj_w, p_wxh);

    // 1) xz = X @ in_proj_w^T   [8192,2048]  (fp16 HMMA, fp16 out)
    mma_gemm_kernel<128,1><<<dim3(2 * DI / 128, ML / 128), 256, GSMEM128>>>(
        p_xh, p_w1h, p_xzh, DM, 2 * DI);

    // 2) u = silu(conv(x)+b)  (fp16 in/out)
    conv_silu_kernel<<<(ML * DI / 4) / 256, 256>>>(p_xzh, conv_w, conv_b, p_uh);

    // 3) x_dbl = u @ x_proj_w^T   [8192,64]  (fp16 HMMA, BN=64; B/C interleaved)
    mma_gemm_kernel<64,0><<<dim3(1, ML / 128), 256, GSMEM64>>>(
        p_uh, p_wxh, p_xdbl, DI, 64);

    // 4) dtduh = packed fp16 (softplus(dt), dt*u)
    sgemm_dt_kernel<<<dim3(DI / 64, ML / 128), 256>>>(p_xdbl, dt_proj_w, dt_proj_b, p_uh, p_dtduh);

    // 5) selective scan -> fp16 ys
    scan_kernel<<<BB * DI / 8, 64>>>(p_dtduh, p_xdbl, A_log, p_ysh);

    // 6) gate -> fp16 y
    gate_kernel<<<(ML * DI) / 256, 256>>>(p_ysh, p_uh, p_xzh, D_skip, p_yh);

    // 7) out = y @ out_proj_w^T  (fp16 HMMA, fp32 out)
    mma_gemm_kernel<128,0><<<dim3(DM / 128, ML / 128), 256, GSMEM128>>>(
        p_yh, p_w2h, out, DI, DM);

    // 8) LayerNorm in place
    ln_kernel<<<ML, 128>>>(out, ln_w, ln_b);
}

// round 17
// speedup vs baseline: 1.0200x; 1.0200x over previous
#include <cuda_runtime.h>
#include <cuda_bf16.h>
#include <cuda_fp16.h>
#include <cstdint>
#include <cstddef>

// Problem constants
#define BB 4
#define LL 2048
#define DM 512
#define DI 1024            // D_INNER
#define DS 16              // D_STATE
#define DTR 32             // DT_RANK
#define ML (BB*LL)         // 8192 rows

// ---------------- scratch (no allocations allowed) ----------------
__device__ float g_xdbl[(size_t)ML * 64];       // 0..31 dt_lr, 32+2n=B_n, 33+2n=C_n

__device__ __align__(256) __half g_xzh[(size_t)ML * 2 * DI];  // in_proj out (x|z), fp16
__device__ __align__(256) __half2 g_dtduh[(size_t)ML * DI];   // (dt, dt*u) packed fp16
__device__ __align__(256) __half g_ysh[(size_t)ML * DI];      // scan output, fp16
__device__ __align__(256) __half g_xh [(size_t)ML * DM];
__device__ __align__(256) __half g_w1h[(size_t)2 * DI * DM];
__device__ __align__(256) __half g_uh [(size_t)ML * DI];
__device__ __align__(256) __half g_wxh[(size_t)64 * DI];
__device__ __align__(256) __half g_yh [(size_t)ML * DI];
__device__ __align__(256) __half g_w2h[(size_t)DM * DI];

// ---------------- PTX helpers (base ISA only) ----------------
__device__ __forceinline__ uint32_t smem_u32(const void* p) {
    uint32_t a;
    asm("{ .reg .u64 t; cvta.to.shared.u64 t, %1; cvt.u32.u64 %0, t; }" : "=r"(a) : "l"(p));
    return a;
}
__device__ __forceinline__ void cp_async16(uint32_t saddr, const void* gaddr) {
    asm volatile("cp.async.cg.shared.global [%0], [%1], 16;" :: "r"(saddr), "l"(gaddr));
}
__device__ __forceinline__ void ldm_x4(uint32_t* r, uint32_t addr) {
    asm volatile("ldmatrix.sync.aligned.m8n8.x4.shared.b16 {%0,%1,%2,%3}, [%4];"
                 : "=r"(r[0]), "=r"(r[1]), "=r"(r[2]), "=r"(r[3]) : "r"(addr));
}
__device__ __forceinline__ void ldm_x2(uint32_t* r, uint32_t addr) {
    asm volatile("ldmatrix.sync.aligned.m8n8.x2.shared.b16 {%0,%1}, [%2];"
                 : "=r"(r[0]), "=r"(r[1]) : "r"(addr));
}
__device__ __forceinline__ void mma_f16(float* d, const uint32_t* a, const uint32_t* b) {
    asm volatile(
        "mma.sync.aligned.m16n8k16.row.col.f32.f16.f16.f32 "
        "{%0,%1,%2,%3}, {%4,%5,%6,%7}, {%8,%9}, {%0,%1,%2,%3};"
        : "+f"(d[0]), "+f"(d[1]), "+f"(d[2]), "+f"(d[3])
        : "r"(a[0]), "r"(a[1]), "r"(a[2]), "r"(a[3]), "r"(b[0]), "r"(b[1]));
}
__device__ __forceinline__ float ex2f(float x) {
    float y;
    asm("ex2.approx.f32 %0, %1;" : "=f"(y) : "f"(x));
    return y;
}
// XOR swizzle for 64B rows: conflict-free for 16B cp.async writes + ldmatrix
__device__ __forceinline__ uint32_t sw64(uint32_t o) { return o ^ ((o >> 3) & 0x30); }

// ---------------- math helpers ----------------
__device__ __forceinline__ float softplusf(float x) {
    return (x > 20.f) ? x : log1pf(__expf(x));
}
__device__ __forceinline__ float siluf(float x) {
    return x * __frcp_rn(1.f + __expf(-x));
}

// ---- fp32 -> fp16 convert: 3 plain arrays + x_proj_w (with B/C row permute) --
__global__ void cvt4_half_kernel(const float* __restrict__ a, __half* __restrict__ ha, int na4,
                                 const float* __restrict__ b, __half* __restrict__ hb, int nb4,
                                 const float* __restrict__ c, __half* __restrict__ hc, int nc4,
                                 const float* __restrict__ wx, __half* __restrict__ hwx) {
    int i = blockIdx.x * 256 + threadIdx.x;
    int nabc = na4 + nb4 + nc4;
    if (i < nabc) {
        const float* src; __half* dst; int off;
        if (i < na4) { src = a; dst = ha; off = i; }
        else if (i < na4 + nb4) { src = b; dst = hb; off = i - na4; }
        else { src = c; dst = hc; off = i - na4 - nb4; }
        float4 v = ((const float4*)src)[off];
        __half2 h0 = __floats2half2_rn(v.x, v.y);
        __half2 h1 = __floats2half2_rn(v.z, v.w);
        ((__half2*)dst)[off * 2 + 0] = h0;
        ((__half2*)dst)[off * 2 + 1] = h1;
        return;
    }
    int j = i - nabc;                 // over 64*DI/4 float4s of x_proj_w
    if (j >= 64 * DI / 4) return;
    int row = j / (DI / 4);
    int off = j % (DI / 4);
    int dst = (row < 32) ? row : ((row < 48) ? 32 + 2 * (row - 32) : 33 + 2 * (row - 48));
    float4 v = ((const float4*)wx)[j];
    __half2 h0 = __floats2half2_rn(v.x, v.y);
    __half2 h1 = __floats2half2_rn(v.z, v.w);
    ((__half2*)(hwx + (size_t)dst * DI))[off * 2 + 0] = h0;
    ((__half2*)(hwx + (size_t)dst * DI))[off * 2 + 1] = h1;
}

// ---------------- HMMA fp16 GEMM (BM x BN tiles; HOUT: fp16/fp32 out) --------
template <int BM, int BN, int HOUT>
__global__ __launch_bounds__(256) void mma_gemm_kernel(
    const __half* __restrict__ A, const __half* __restrict__ B,
    void* __restrict__ Cv, int K, int ldc) {
    constexpr int NWN = (BN == 128) ? 4 : 2;
    constexpr int NWM = 8 / NWN;
    constexpr int MT = (BM / NWM) / 16;
    constexpr int NT = (BN / NWN) / 8;
    constexpr int ATB = BM * 64;
    constexpr int BTB = BN * 64;
    constexpr int STG = ATB + BTB;
    constexpr int ASEGS = BM * 4;
    constexpr int NSEG = (BM + BN) * 4;

    extern __shared__ __align__(128) char smem[];
    const int tid = threadIdx.x;
    const int lane = tid & 31;
    const int wid = tid >> 5;
    const int warp_m = wid / NWN;
    const int warp_n = wid % NWN;
    const int bm = blockIdx.y * BM;
    const int bn = blockIdx.x * BN;

    uint32_t sb = smem_u32(smem);
    const __half* gpa = A + (size_t)bm * K;
    const __half* gpb = B + (size_t)bn * K;

    float acc[MT][NT][4];
#pragma unroll
    for (int i = 0; i < MT; i++)
#pragma unroll
        for (int j = 0; j < NT; j++)
#pragma unroll
            for (int v = 0; v < 4; v++) acc[i][j][v] = 0.f;

    const int nch = K >> 5;

#define GLOAD(stage_, k0_)                                                          \
    {                                                                               \
        _Pragma("unroll")                                                           \
        for (int i = 0; i < NSEG / 256; i++) {                                      \
            int seg = tid + i * 256;                                                \
            int q = seg & 3;                                                        \
            uint32_t soff; const __half* g;                                         \
            if (seg < ASEGS) {                                                      \
                int r_ = seg >> 2;                                                  \
                soff = sw64(r_ * 64 + q * 16);                                      \
                g = gpa + (size_t)r_ * K + (k0_) + q * 8;                           \
            } else {                                                                \
                int r_ = (seg - ASEGS) >> 2;                                        \
                soff = ATB + sw64(r_ * 64 + q * 16);                                \
                g = gpb + (size_t)r_ * K + (k0_) + q * 8;                           \
            }                                                                       \
            cp_async16(sb + (stage_) * STG + soff, g);                              \
        }                                                                           \
        asm volatile("cp.async.commit_group;");                                     \
    }

    GLOAD(0, 0);
    if (nch > 1) GLOAD(1, 32);

    const int arow = warp_m * (MT * 16) + (lane & 15);
    const int acolb = (lane >> 4) * 16;
    const int brow = warp_n * (NT * 8) + (lane & 7);
    const int bcolb = ((lane >> 3) & 1) * 16;

    for (int c = 0; c < nch; c++) {
        const int s = c % 3;
        if (c + 2 < nch) {
            GLOAD((c + 2) % 3, (c + 2) << 5);
            asm volatile("cp.async.wait_group 2;" ::: "memory");
        } else if (c + 1 < nch) {
            asm volatile("cp.async.wait_group 1;" ::: "memory");
        } else {
            asm volatile("cp.async.wait_group 0;" ::: "memory");
        }
        __syncthreads();

        uint32_t base = sb + s * STG;
#pragma unroll
        for (int ks = 0; ks < 2; ks++) {
            uint32_t a_f[MT][4], b_f[NT][2];
#pragma unroll
            for (int im = 0; im < MT; im++) {
                uint32_t off = sw64((arow + im * 16) * 64 + ks * 32 + acolb);
                ldm_x4(a_f[im], base + off);
            }
#pragma unroll
            for (int jn = 0; jn < NT; jn++) {
                uint32_t off = sw64((brow + jn * 8) * 64 + ks * 32 + bcolb);
                ldm_x2(b_f[jn], base + ATB + off);
            }
#pragma unroll
            for (int im = 0; im < MT; im++)
#pragma unroll
                for (int jn = 0; jn < NT; jn++)
                    mma_f16(acc[im][jn], a_f[im], b_f[jn]);
        }
        __syncthreads();
    }
#undef GLOAD

#pragma unroll
    for (int im = 0; im < MT; im++) {
        int r0 = bm + warp_m * (MT * 16) + im * 16 + (lane >> 2);
#pragma unroll
        for (int jn = 0; jn < NT; jn++) {
            int col = bn + warp_n * (NT * 8) + jn * 8 + (lane & 3) * 2;
            if (HOUT) {
                __half* Ch = (__half*)Cv;
                __half2 v0 = __floats2half2_rn(acc[im][jn][0], acc[im][jn][1]);
                __half2 v1 = __floats2half2_rn(acc[im][jn][2], acc[im][jn][3]);
                *(__half2*)(Ch + (size_t)r0 * ldc + col) = v0;
                *(__half2*)(Ch + (size_t)(r0 + 8) * ldc + col) = v1;
            } else {
                float* C = (float*)Cv;
                float2 v0; v0.x = acc[im][jn][0]; v0.y = acc[im][jn][1];
                float2 v1; v1.x = acc[im][jn][2]; v1.y = acc[im][jn][3];
                *(float2*)(C + (size_t)r0 * ldc + col) = v0;
                *(float2*)(C + (size_t)(r0 + 8) * ldc + col) = v1;
            }
        }
    }
}

#define GSMEM128 (3 * (128 * 64 + 128 * 64))  // 49152
#define GSMEM64  (3 * (64 * 64 + 64 * 64))    // 24576

// ----- dt SGEMM (K=32): dt = softplus(x_dbl[:,0:32] @ dt_proj_w^T + b)
// reads u as fp16; writes packed __half2 (dt, dt*u) into dtduh
__global__ void sgemm_dt_kernel(const float* __restrict__ A, const float* __restrict__ W,
                                const float* __restrict__ bias, const __half* __restrict__ uh,
                                __half2* __restrict__ dtduh) {
    __shared__ float As[16 * 132];
    __shared__ float Bs[16 * 68];
    const int tid = threadIdx.x;
    const int tx = tid & 15;
    const int ty = tid >> 4;
    const int bm = blockIdx.y * 128;
    const int bn = blockIdx.x * 64;

    const float* Ab = A + (size_t)bm * 64;
    const float* Wb = W + (size_t)bn * DTR;

    float acc[8][4];
#pragma unroll
    for (int i = 0; i < 8; i++)
#pragma unroll
        for (int j = 0; j < 4; j++) acc[i][j] = 0.f;

    for (int k0 = 0; k0 < DTR; k0 += 16) {
#pragma unroll
        for (int i = 0; i < 2; i++) {
            int qid = tid + i * 256;
            int r = qid >> 2, q = qid & 3;
            float4 v = *(const float4*)(Ab + (size_t)r * 64 + k0 + q * 4);
            As[(q * 4 + 0) * 132 + r] = v.x;
            As[(q * 4 + 1) * 132 + r] = v.y;
            As[(q * 4 + 2) * 132 + r] = v.z;
            As[(q * 4 + 3) * 132 + r] = v.w;
        }
        {
            int r = tid >> 2, q = tid & 3;
            float4 v = *(const float4*)(Wb + (size_t)r * DTR + k0 + q * 4);
            Bs[(q * 4 + 0) * 68 + r] = v.x;
            Bs[(q * 4 + 1) * 68 + r] = v.y;
            Bs[(q * 4 + 2) * 68 + r] = v.z;
            Bs[(q * 4 + 3) * 68 + r] = v.w;
        }
        __syncthreads();
#pragma unroll
        for (int k = 0; k < 16; k++) {
            float4 a0 = *(const float4*)(As + k * 132 + ty * 8);
            float4 a1 = *(const float4*)(As + k * 132 + ty * 8 + 4);
            float4 b0 = *(const float4*)(Bs + k * 68 + tx * 4);
            float a[8] = {a0.x, a0.y, a0.z, a0.w, a1.x, a1.y, a1.z, a1.w};
            float bb[4] = {b0.x, b0.y, b0.z, b0.w};
#pragma unroll
            for (int i = 0; i < 8; i++)
#pragma unroll
                for (int j = 0; j < 4; j++) acc[i][j] = fmaf(a[i], bb[j], acc[i][j]);
        }
        __syncthreads();
    }

#pragma unroll
    for (int i = 0; i < 8; i++) {
        int row = bm + ty * 8 + i;
        int col = bn + tx * 4;
        __half2 u01 = *(const __half2*)(uh + (size_t)row * DI + col);
        __half2 u23 = *(const __half2*)(uh + (size_t)row * DI + col + 2);
        float u0 = __half2float(u01.x), u1 = __half2float(u01.y);
        float u2 = __half2float(u23.x), u3 = __half2float(u23.y);
        float d0 = softplusf(acc[i][0] + bias[col + 0]);
        float d1 = softplusf(acc[i][1] + bias[col + 1]);
        float d2 = softplusf(acc[i][2] + bias[col + 2]);
        float d3 = softplusf(acc[i][3] + bias[col + 3]);
        __half2 p0 = __floats2half2_rn(d0, d0 * u0);
        __half2 p1 = __floats2half2_rn(d1, d1 * u1);
        __half2 p2 = __floats2half2_rn(d2, d2 * u2);
        __half2 p3 = __floats2half2_rn(d3, d3 * u3);
        uint4 pk;
        pk.x = *(uint32_t*)&p0; pk.y = *(uint32_t*)&p1;
        pk.z = *(uint32_t*)&p2; pk.w = *(uint32_t*)&p3;
        *(uint4*)(dtduh + (size_t)row * DI + col) = pk;
    }
}

// ------- depthwise causal conv + bias + SiLU; 4 timesteps/thread -------------
__global__ void conv_silu_kernel(const __half* __restrict__ xzh, const float* __restrict__ w,
                                 const float* __restrict__ b, __half* __restrict__ uh) {
    int idx = blockIdx.x * 256 + threadIdx.x;     // ML*DI/4 threads
    if (idx >= ML * DI / 4) return;
    int d = idx & (DI - 1);
    int t4 = idx >> 10;                           // 0..2047
    int bb = t4 >> 9;
    int l0 = (t4 & 511) * 4;
    size_t base = ((size_t)bb * LL + l0) * (2 * DI) + d;

    float w0 = w[d * 4 + 0], w1 = w[d * 4 + 1], w2 = w[d * 4 + 2], w3 = w[d * 4 + 3];
    float bias = b[d];

    float xm3 = 0.f, xm2 = 0.f, xm1 = 0.f;
    if (l0 > 0) {
        xm3 = __half2float(xzh[base - 3 * (size_t)(2 * DI)]);
        xm2 = __half2float(xzh[base - 2 * (size_t)(2 * DI)]);
        xm1 = __half2float(xzh[base - 1 * (size_t)(2 * DI)]);
    }
    float x0 = __half2float(xzh[base + 0 * (size_t)(2 * DI)]);
    float x1 = __half2float(xzh[base + 1 * (size_t)(2 * DI)]);
    float x2 = __half2float(xzh[base + 2 * (size_t)(2 * DI)]);
    float x3 = __half2float(xzh[base + 3 * (size_t)(2 * DI)]);

    float s0 = siluf(fmaf(w3, x0, fmaf(w2, xm1, fmaf(w1, xm2, fmaf(w0, xm3, bias)))));
    float s1 = siluf(fmaf(w3, x1, fmaf(w2, x0,  fmaf(w1, xm1, fmaf(w0, xm2, bias)))));
    float s2 = siluf(fmaf(w3, x2, fmaf(w2, x1,  fmaf(w1, x0,  fmaf(w0, xm1, bias)))));
    float s3 = siluf(fmaf(w3, x3, fmaf(w2, x2,  fmaf(w1, x1,  fmaf(w0, x0,  bias)))));

    size_t ob = ((size_t)bb * LL + l0) * DI + d;
    uh[ob + 0 * DI] = __float2half_rn(s0);
    uh[ob + 1 * DI] = __float2half_rn(s1);
    uh[ob + 2 * DI] = __float2half_rn(s2);
    uh[ob + 3 * DI] = __float2half_rn(s3);
}

// ------- selective scan: 8 lanes/channel, 2 states/lane, SW-pipelined --------
#define SU 8
__global__ __launch_bounds__(64) void scan_kernel(
    const __half2* __restrict__ dtduh, const float* __restrict__ xdbl,
    const float* __restrict__ A_log, __half* __restrict__ ysh) {
    int grp = threadIdx.x >> 3;       // 8 channel-groups per 64-thread block
    int sub = threadIdx.x & 7;        // lane within channel (states 2sub, 2sub+1)
    int ch = blockIdx.x * 8 + grp;
    int b = ch >> 10;
    int d = ch & (DI - 1);

    const float LOG2E = 1.4426950408889634f;
    float An0 = -__expf(A_log[d * DS + 2 * sub + 0]) * LOG2E;
    float An1 = -__expf(A_log[d * DS + 2 * sub + 1]) * LOG2E;

    const __half2* ddp = dtduh + (size_t)b * LL * DI + d;                           // +t*DI
    const float4* bcp = (const float4*)(xdbl + (size_t)b * LL * 64 + 32 + 4 * sub); // +t*16
    __half* yp = ysh + (size_t)b * LL * DI + d;

    float h0 = 0.f, h1 = 0.f;
    __half2 cdd[SU]; float4 cbc[SU];
#pragma unroll
    for (int j = 0; j < SU; j++) {
        cdd[j] = __ldg(ddp + (size_t)j * DI);
        cbc[j] = __ldg(bcp + (size_t)j * 16);
    }
    for (int t0 = 0; t0 < LL; t0 += SU) {
        __half2 ndd[SU]; float4 nbc[SU];
        if (t0 + SU < LL) {
#pragma unroll
            for (int j = 0; j < SU; j++) {
                size_t o = (size_t)(t0 + SU + j);
                ndd[j] = __ldg(ddp + o * DI);
                nbc[j] = __ldg(bcp + o * 16);
            }
        }
#pragma unroll
        for (int j = 0; j < SU; j++) {
            float dt  = __half2float(cdd[j].x);
            float dtu = __half2float(cdd[j].y);
            float dA0 = ex2f(dt * An0);
            float dA1 = ex2f(dt * An1);
            h0 = fmaf(dA0, h0, dtu * cbc[j].x);   // B_2s
            h1 = fmaf(dA1, h1, dtu * cbc[j].z);   // B_2s+1
            float p = fmaf(h1, cbc[j].w, h0 * cbc[j].y);
            p += __shfl_xor_sync(0xffffffffu, p, 4, 8);
            p += __shfl_xor_sync(0xffffffffu, p, 2, 8);
            p += __shfl_xor_sync(0xffffffffu, p, 1, 8);
            if (sub == 0) yp[(size_t)(t0 + j) * DI] = __float2half_rn(p);
        }
#pragma unroll
        for (int j = 0; j < SU; j++) { cdd[j] = ndd[j]; cbc[j] = nbc[j]; }
    }
}

// ------- gate: y = (ys + u*D) * silu(z) -> fp16 (all streams fp16) -----------
__global__ void gate_kernel(const __half* __restrict__ ysh, const __half* __restrict__ uh,
                            const __half* __restrict__ xzh, const float* __restrict__ Dskip,
                            __half* __restrict__ yh) {
    int idx = blockIdx.x * 256 + threadIdx.x;
    if (idx >= ML * DI) return;
    int d = idx & (DI - 1);
    size_t bl = (size_t)(idx >> 10);
    float z = __half2float(xzh[bl * (2 * DI) + DI + d]);
    float u = __half2float(uh[idx]);
    float ysv = __half2float(ysh[idx]);
    float y = fmaf(u, Dskip[d], ysv) * siluf(z);
    yh[idx] = __float2half_rn(y);
}

// ---------------- LayerNorm ---------------------------------------
__global__ void ln_kernel(float* __restrict__ io, const float* __restrict__ w,
                          const float* __restrict__ b) {
    __shared__ float ssum[4], ssq[4];
    int row = blockIdx.x;
    float* p = io + (size_t)row * DM;
    int t = threadIdx.x;
    float4 v = ((float4*)p)[t];
    float s = v.x + v.y + v.z + v.w;
    float q = v.x * v.x + v.y * v.y + v.z * v.z + v.w * v.w;
#pragma unroll
    for (int o = 16; o; o >>= 1) {
        s += __shfl_xor_sync(0xffffffffu, s, o);
        q += __shfl_xor_sync(0xffffffffu, q, o);
    }
    if ((t & 31) == 0) { ssum[t >> 5] = s; ssq[t >> 5] = q; }
    __syncthreads();
    s = ssum[0] + ssum[1] + ssum[2] + ssum[3];
    q = ssq[0] + ssq[1] + ssq[2] + ssq[3];
    float mu = s * (1.f / DM);
    float var = q * (1.f / DM) - mu * mu;
    float inv = rsqrtf(var + 1e-5f);
    int c = t * 4;
    float4 o;
    o.x = (v.x - mu) * inv * w[c + 0] + b[c + 0];
    o.y = (v.y - mu) * inv * w[c + 1] + b[c + 1];
    o.z = (v.z - mu) * inv * w[c + 2] + b[c + 2];
    o.w = (v.w - mu) * inv * w[c + 3] + b[c + 3];
    ((float4*)p)[t] = o;
}

// ---------------- launch ------------------------------------------
extern "C" void kernel_launch(void* const* d_in, const int* in_sizes, int n_in,
                              void* d_out, int out_size) {
    const float* x_in      = (const float*)d_in[0];
    const float* in_proj_w = (const float*)d_in[1];
    const float* conv_w    = (const float*)d_in[2];
    const float* conv_b    = (const float*)d_in[3];
    const float* x_proj_w  = (const float*)d_in[4];
    const float* dt_proj_w = (const float*)d_in[5];
    const float* dt_proj_b = (const float*)d_in[6];
    const float* A_log     = (const float*)d_in[7];
    const float* D_skip    = (const float*)d_in[8];
    const float* out_proj_w= (const float*)d_in[9];
    const float* ln_w      = (const float*)d_in[10];
    const float* ln_b      = (const float*)d_in[11];
    float* out = (float*)d_out;

    static float *p_xdbl=nullptr;
    static __half2 *p_dtduh;
    static __half *p_xzh,*p_ysh,*p_xh,*p_w1h,*p_uh,*p_wxh,*p_yh,*p_w2h;
    if (!p_xdbl) {
        cudaGetSymbolAddress((void**)&p_xdbl, g_xdbl);
        cudaGetSymbolAddress((void**)&p_xzh, g_xzh);
        cudaGetSymbolAddress((void**)&p_dtduh, g_dtduh);
        cudaGetSymbolAddress((void**)&p_ysh, g_ysh);
        cudaGetSymbolAddress((void**)&p_xh, g_xh);
        cudaGetSymbolAddress((void**)&p_w1h, g_w1h);
        cudaGetSymbolAddress((void**)&p_uh, g_uh);
        cudaGetSymbolAddress((void**)&p_wxh, g_wxh);
        cudaGetSymbolAddress((void**)&p_yh, g_yh);
        cudaGetSymbolAddress((void**)&p_w2h, g_w2h);
        cudaFuncSetAttribute((const void*)mma_gemm_kernel<128,128,0>, cudaFuncAttributeMaxDynamicSharedMemorySize, GSMEM128);
        cudaFuncSetAttribute((const void*)mma_gemm_kernel<128,128,1>, cudaFuncAttributeMaxDynamicSharedMemorySize, GSMEM128);
        cudaFuncSetAttribute((const void*)mma_gemm_kernel<64,64,0>,   cudaFuncAttributeMaxDynamicSharedMemorySize, GSMEM64);
    }

    // 0) fp16 converts: 3 plain arrays + permuted x_proj_w in ONE launch
    const int na4 = ML * DM / 4, nb4 = 2 * DI * DM / 4, nc4 = DM * DI / 4;
    const int nwx4 = 64 * DI / 4;
    cvt4_half_kernel<<<(na4 + nb4 + nc4 + nwx4 + 255) / 256, 256>>>(
        x_in, p_xh, na4, in_proj_w, p_w1h, nb4, out_proj_w, p_w2h, nc4, x_proj_w, p_wxh);

    // 1) xz = X @ in_proj_w^T   [8192,2048]  (fp16 HMMA, fp16 out)
    mma_gemm_kernel<128,128,1><<<dim3(2 * DI / 128, ML / 128), 256, GSMEM128>>>(
        p_xh, p_w1h, p_xzh, DM, 2 * DI);

    // 2) u = silu(conv(x)+b)  (fp16 in/out)
    conv_silu_kernel<<<(ML * DI / 4) / 256, 256>>>(p_xzh, conv_w, conv_b, p_uh);

    // 3) x_dbl = u @ x_proj_w^T   [8192,64]  (fp16 HMMA; BM=64 -> 128 CTAs)
    mma_gemm_kernel<64,64,0><<<dim3(1, ML / 64), 256, GSMEM64>>>(
        p_uh, p_wxh, p_xdbl, DI, 64);

    // 4) dtduh = packed fp16 (softplus(dt), dt*u)
    sgemm_dt_kernel<<<dim3(DI / 64, ML / 128), 256>>>(p_xdbl, dt_proj_w, dt_proj_b, p_uh, p_dtduh);

    // 5) selective scan -> fp16 ys
    scan_kernel<<<BB * DI / 8, 64>>>(p_dtduh, p_xdbl, A_log, p_ysh);

    // 6) gate -> fp16 y
    gate_kernel<<<(ML * DI) / 256, 256>>>(p_ysh, p_uh, p_xzh, D_skip, p_yh);

    // 7) out = y @ out_proj_w^T  (fp16 HMMA, fp32 out)
    mma_gemm_kernel<128,128,0><<<dim3(DM / 128, ML / 128), 256, GSMEM128>>>(
        p_yh, p_w2h, out, DI, DM);

    // 8) LayerNorm in place
    ln_kernel<<<ML, 128>>>(out, ln_w, ln_b);
}